// round 1
// baseline (speedup 1.0000x reference)
#include <cuda_runtime.h>
#include <math.h>

#define DIM   1024
#define HID   2048
#define NE    8
#define TMAX  8192
#define NSLOT (TMAX * 2)

// ---------------- static device scratch (no allocations allowed) ----------------
__device__ int   g_counts[NE];
__device__ int   g_lists[NE * TMAX];     // entries are slot = token*2 + k
__device__ float g_wslot[NSLOT];         // combine weight per slot
__device__ float g_hbuf[(size_t)NSLOT * HID];  // 128 MB hidden activations

__device__ __forceinline__ float gelu_exact(float v) {
    return 0.5f * v * (1.0f + erff(v * 0.7071067811865476f));
}

// ---------------- kernel 0: zero routing counters ----------------
__global__ void zero_counts_kernel() {
    if (threadIdx.x < NE) g_counts[threadIdx.x] = 0;
}

// ---------------- kernel 1: gating (logits, softmax top-2, routing) ----------------
// 1 block per token, 256 threads (8 warps -> 8 experts)
__global__ void __launch_bounds__(256) gating_kernel(
    const float* __restrict__ x, const float* __restrict__ gw,
    const float* __restrict__ gb, float* __restrict__ logits_out)
{
    const int t = blockIdx.x;
    __shared__ float sx[DIM];
    __shared__ float slog[NE];

    const int tid = threadIdx.x;
    const float* xr = x + (size_t)t * DIM;
    #pragma unroll 2
    for (int i = tid; i < DIM; i += 256) sx[i] = xr[i];
    __syncthreads();

    const int w = tid >> 5, lane = tid & 31;
    const float* gwr = gw + (size_t)w * DIM;
    float s = 0.0f;
    #pragma unroll 8
    for (int i = lane; i < DIM; i += 32) s += sx[i] * gwr[i];
    #pragma unroll
    for (int o = 16; o > 0; o >>= 1) s += __shfl_down_sync(0xffffffffu, s, o);
    if (lane == 0) {
        s += gb[w];
        slog[w] = s;
        if (logits_out) logits_out[(size_t)t * NE + w] = s;
    }
    __syncthreads();

    if (tid == 0) {
        // top-1 (first index wins on ties, matching lax.top_k)
        int i0 = 0; float v0 = slog[0];
        #pragma unroll
        for (int i = 1; i < NE; i++) if (slog[i] > v0) { v0 = slog[i]; i0 = i; }
        // top-2
        int i1 = -1; float v1 = -3.4e38f;
        #pragma unroll
        for (int i = 0; i < NE; i++) if (i != i0 && slog[i] > v1) { v1 = slog[i]; i1 = i; }
        // renormalized top-2 softmax == 2-way softmax over (v0, v1)
        float r  = expf(v1 - v0);
        float w0 = 1.0f / (1.0f + r);
        float w1 = r * w0;

        int p0 = atomicAdd(&g_counts[i0], 1);
        g_lists[i0 * TMAX + p0] = t * 2;
        int p1 = atomicAdd(&g_counts[i1], 1);
        g_lists[i1 * TMAX + p1] = t * 2 + 1;
        g_wslot[t * 2]     = w0;
        g_wslot[t * 2 + 1] = w1;
    }
}

// ---------------- kernel 2: gathered GEMM1 + bias + exact GELU -> h_buf ----------------
// C[m, n] = gelu( x[tok(m)] . W1[e][:, n] + b1[e][n] ),  tile 128x128, BK=8
__global__ void __launch_bounds__(256) gemm1_kernel(
    const float* __restrict__ x, const float* __restrict__ W1,
    const float* __restrict__ b1)
{
    const int e   = blockIdx.z;
    const int cnt = g_counts[e];
    const int m0  = blockIdx.y * 128;
    if (m0 >= cnt) return;
    const int n0 = blockIdx.x * 128;
    const float* __restrict__ B = W1 + (size_t)e * DIM * HID;

    __shared__ float As[8][128];
    __shared__ float Bs[8][128];
    __shared__ int   sSlot[128];

    const int tid = threadIdx.x;
    if (tid < 128) {
        int gr = m0 + tid;
        sSlot[tid] = (gr < cnt) ? g_lists[e * TMAX + gr] : -1;
    }
    __syncthreads();

    const int arow  = tid & 127;
    const int apart = tid >> 7;                 // k sub-offset 0 or 4
    const int aslot = sSlot[arow];
    const float* aptr = (aslot >= 0) ? (x + (size_t)(aslot >> 1) * DIM + apart * 4) : (const float*)0;

    const int brow = tid >> 5;
    const int bcol = (tid & 31) * 4;
    const float* bptr = B + (size_t)brow * HID + n0 + bcol;

    const int tx = tid & 15;
    const int ty = tid >> 4;

    float acc[2][2][4][4];
    #pragma unroll
    for (int a_ = 0; a_ < 2; a_++)
        #pragma unroll
        for (int b_ = 0; b_ < 2; b_++)
            #pragma unroll
            for (int i = 0; i < 4; i++)
                #pragma unroll
                for (int j = 0; j < 4; j++) acc[a_][b_][i][j] = 0.0f;

    for (int k0 = 0; k0 < DIM; k0 += 8) {
        float4 av = make_float4(0.f, 0.f, 0.f, 0.f);
        if (aptr) av = *(const float4*)(aptr + k0);
        float4 bv = *(const float4*)(bptr + (size_t)k0 * HID);
        __syncthreads();
        As[apart * 4 + 0][arow] = av.x;
        As[apart * 4 + 1][arow] = av.y;
        As[apart * 4 + 2][arow] = av.z;
        As[apart * 4 + 3][arow] = av.w;
        *(float4*)&Bs[brow][bcol] = bv;
        __syncthreads();

        #pragma unroll
        for (int kk = 0; kk < 8; kk++) {
            float a[2][4], b[2][4];
            float4 t0 = *(const float4*)&As[kk][ty * 4];
            float4 t1 = *(const float4*)&As[kk][64 + ty * 4];
            a[0][0] = t0.x; a[0][1] = t0.y; a[0][2] = t0.z; a[0][3] = t0.w;
            a[1][0] = t1.x; a[1][1] = t1.y; a[1][2] = t1.z; a[1][3] = t1.w;
            float4 u0 = *(const float4*)&Bs[kk][tx * 4];
            float4 u1 = *(const float4*)&Bs[kk][64 + tx * 4];
            b[0][0] = u0.x; b[0][1] = u0.y; b[0][2] = u0.z; b[0][3] = u0.w;
            b[1][0] = u1.x; b[1][1] = u1.y; b[1][2] = u1.z; b[1][3] = u1.w;
            #pragma unroll
            for (int rh = 0; rh < 2; rh++)
                #pragma unroll
                for (int i = 0; i < 4; i++)
                    #pragma unroll
                    for (int ch = 0; ch < 2; ch++)
                        #pragma unroll
                        for (int j = 0; j < 4; j++)
                            acc[rh][ch][i][j] += a[rh][i] * b[ch][j];
        }
    }

    float bias[2][4];
    #pragma unroll
    for (int ch = 0; ch < 2; ch++)
        #pragma unroll
        for (int j = 0; j < 4; j++)
            bias[ch][j] = b1[(size_t)e * HID + n0 + ch * 64 + tx * 4 + j];

    #pragma unroll
    for (int rh = 0; rh < 2; rh++)
        #pragma unroll
        for (int i = 0; i < 4; i++) {
            int lr = rh * 64 + ty * 4 + i;
            if (m0 + lr < cnt) {
                float* hrow = g_hbuf + (size_t)sSlot[lr] * HID + n0;
                #pragma unroll
                for (int ch = 0; ch < 2; ch++) {
                    float4 hv;
                    hv.x = gelu_exact(acc[rh][ch][i][0] + bias[ch][0]);
                    hv.y = gelu_exact(acc[rh][ch][i][1] + bias[ch][1]);
                    hv.z = gelu_exact(acc[rh][ch][i][2] + bias[ch][2]);
                    hv.w = gelu_exact(acc[rh][ch][i][3] + bias[ch][3]);
                    *(float4*)(hrow + ch * 64 + tx * 4) = hv;
                }
            }
        }
}

// ---------------- kernel 3: GEMM2 + bias, weighted atomic scatter to out ----------------
// out[tok(m), n] += w(m) * ( h[m] . W2[e][:, n] + b2[e][n] )
__global__ void __launch_bounds__(256) gemm2_kernel(
    const float* __restrict__ W2, const float* __restrict__ b2,
    float* __restrict__ out)
{
    const int e   = blockIdx.z;
    const int cnt = g_counts[e];
    const int m0  = blockIdx.y * 128;
    if (m0 >= cnt) return;
    const int n0 = blockIdx.x * 128;
    const float* __restrict__ B = W2 + (size_t)e * HID * DIM;

    __shared__ float As[8][128];
    __shared__ float Bs[8][128];
    __shared__ int   sSlot[128];

    const int tid = threadIdx.x;
    if (tid < 128) {
        int gr = m0 + tid;
        sSlot[tid] = (gr < cnt) ? g_lists[e * TMAX + gr] : -1;
    }
    __syncthreads();

    const int arow  = tid & 127;
    const int apart = tid >> 7;
    const int aslot = sSlot[arow];
    const float* aptr = (aslot >= 0) ? (g_hbuf + (size_t)aslot * HID + apart * 4) : (const float*)0;

    const int brow = tid >> 5;
    const int bcol = (tid & 31) * 4;
    const float* bptr = B + (size_t)brow * DIM + n0 + bcol;

    const int tx = tid & 15;
    const int ty = tid >> 4;

    float acc[2][2][4][4];
    #pragma unroll
    for (int a_ = 0; a_ < 2; a_++)
        #pragma unroll
        for (int b_ = 0; b_ < 2; b_++)
            #pragma unroll
            for (int i = 0; i < 4; i++)
                #pragma unroll
                for (int j = 0; j < 4; j++) acc[a_][b_][i][j] = 0.0f;

    for (int k0 = 0; k0 < HID; k0 += 8) {
        float4 av = make_float4(0.f, 0.f, 0.f, 0.f);
        if (aptr) av = *(const float4*)(aptr + k0);
        float4 bv = *(const float4*)(bptr + (size_t)k0 * DIM);
        __syncthreads();
        As[apart * 4 + 0][arow] = av.x;
        As[apart * 4 + 1][arow] = av.y;
        As[apart * 4 + 2][arow] = av.z;
        As[apart * 4 + 3][arow] = av.w;
        *(float4*)&Bs[brow][bcol] = bv;
        __syncthreads();

        #pragma unroll
        for (int kk = 0; kk < 8; kk++) {
            float a[2][4], b[2][4];
            float4 t0 = *(const float4*)&As[kk][ty * 4];
            float4 t1 = *(const float4*)&As[kk][64 + ty * 4];
            a[0][0] = t0.x; a[0][1] = t0.y; a[0][2] = t0.z; a[0][3] = t0.w;
            a[1][0] = t1.x; a[1][1] = t1.y; a[1][2] = t1.z; a[1][3] = t1.w;
            float4 u0 = *(const float4*)&Bs[kk][tx * 4];
            float4 u1 = *(const float4*)&Bs[kk][64 + tx * 4];
            b[0][0] = u0.x; b[0][1] = u0.y; b[0][2] = u0.z; b[0][3] = u0.w;
            b[1][0] = u1.x; b[1][1] = u1.y; b[1][2] = u1.z; b[1][3] = u1.w;
            #pragma unroll
            for (int rh = 0; rh < 2; rh++)
                #pragma unroll
                for (int i = 0; i < 4; i++)
                    #pragma unroll
                    for (int ch = 0; ch < 2; ch++)
                        #pragma unroll
                        for (int j = 0; j < 4; j++)
                            acc[rh][ch][i][j] += a[rh][i] * b[ch][j];
        }
    }

    float bias[2][4];
    #pragma unroll
    for (int ch = 0; ch < 2; ch++)
        #pragma unroll
        for (int j = 0; j < 4; j++)
            bias[ch][j] = b2[(size_t)e * DIM + n0 + ch * 64 + tx * 4 + j];

    #pragma unroll
    for (int rh = 0; rh < 2; rh++)
        #pragma unroll
        for (int i = 0; i < 4; i++) {
            int lr = rh * 64 + ty * 4 + i;
            if (m0 + lr < cnt) {
                int slot  = sSlot[lr];
                int token = slot >> 1;
                float w   = g_wslot[slot];
                float* orow = out + (size_t)token * DIM + n0;
                #pragma unroll
                for (int ch = 0; ch < 2; ch++) {
                    #pragma unroll
                    for (int j = 0; j < 4; j++) {
                        float v = w * (acc[rh][ch][i][j] + bias[ch][j]);
                        atomicAdd(orow + ch * 64 + tx * 4 + j, v);
                    }
                }
            }
        }
}

// ---------------- launch ----------------
extern "C" void kernel_launch(void* const* d_in, const int* in_sizes, int n_in,
                              void* d_out, int out_size)
{
    const float* x  = (const float*)d_in[0];
    const float* gw = (const float*)d_in[1];
    const float* gb = (const float*)d_in[2];
    const float* W1 = (const float*)d_in[3];
    const float* b1 = (const float*)d_in[4];
    const float* W2 = (const float*)d_in[5];
    const float* b2 = (const float*)d_in[6];
    float* out = (float*)d_out;

    const int T = in_sizes[0] / DIM;  // 8192

    // Output layout: [out (T*DIM floats)] then, if present, [logits (T*NE floats)]
    float* logits = 0;
    if (out_size >= T * DIM + T * NE) logits = out + (size_t)T * DIM;

    cudaMemsetAsync(out, 0, (size_t)T * DIM * sizeof(float), 0);
    zero_counts_kernel<<<1, 32>>>();
    gating_kernel<<<T, 256>>>(x, gw, gb, logits);

    const int mt = (T + 127) / 128;               // worst-case M tiles per expert
    gemm1_kernel<<<dim3(HID / 128, mt, NE), 256>>>(x, W1, b1);
    gemm2_kernel<<<dim3(DIM / 128, mt, NE), 256>>>(W2, b2, out);
}

// round 2
// speedup vs baseline: 2.4797x; 2.4797x over previous
#include <cuda_runtime.h>
#include <math.h>

#define DIM   1024
#define HID   2048
#define NE    8
#define TMAX  8192
#define NSLOT (TMAX * 2)

// ---------------- static device scratch (no allocations allowed) ----------------
__device__ int   g_counts[NE];
__device__ int   g_lists[NE * TMAX];            // entries are slot = token*2 + k
__device__ float g_wslot[NSLOT];                // combine weight per slot
__device__ float g_hbuf[(size_t)NSLOT * HID];   // 128 MB hidden activations

__device__ __forceinline__ float gelu_exact(float v) {
    return 0.5f * v * (1.0f + erff(v * 0.7071067811865476f));
}

__device__ __forceinline__ unsigned f2tf(float f) {
    unsigned u;
    asm("cvt.rna.tf32.f32 %0, %1;" : "=r"(u) : "f"(f));
    return u;
}

__device__ __forceinline__ void mma_tf32(float* c, const unsigned* a, const unsigned* b) {
    asm volatile(
        "mma.sync.aligned.m16n8k8.row.col.f32.tf32.tf32.f32 "
        "{%0,%1,%2,%3}, {%4,%5,%6,%7}, {%8,%9}, {%0,%1,%2,%3};"
        : "+f"(c[0]), "+f"(c[1]), "+f"(c[2]), "+f"(c[3])
        : "r"(a[0]), "r"(a[1]), "r"(a[2]), "r"(a[3]), "r"(b[0]), "r"(b[1]));
}

__device__ __forceinline__ void cp16(void* s, const void* g) {
    unsigned ss = (unsigned)__cvta_generic_to_shared(s);
    asm volatile("cp.async.cg.shared.global [%0], [%1], 16;" :: "r"(ss), "l"(g));
}
#define CP_COMMIT asm volatile("cp.async.commit_group;")
#define CP_WAIT0  asm volatile("cp.async.wait_group 0;")

// ---------------- kernel 0: zero routing counters ----------------
__global__ void zero_counts_kernel() {
    if (threadIdx.x < NE) g_counts[threadIdx.x] = 0;
}

// ---------------- kernel 1: gating (logits, softmax top-2, routing) ----------------
__global__ void __launch_bounds__(256) gating_kernel(
    const float* __restrict__ x, const float* __restrict__ gw,
    const float* __restrict__ gb, float* __restrict__ logits_out)
{
    const int t = blockIdx.x;
    __shared__ float sx[DIM];
    __shared__ float slog[NE];

    const int tid = threadIdx.x;
    const float* xr = x + (size_t)t * DIM;
    #pragma unroll 2
    for (int i = tid; i < DIM; i += 256) sx[i] = xr[i];
    __syncthreads();

    const int w = tid >> 5, lane = tid & 31;
    const float* gwr = gw + (size_t)w * DIM;
    float s = 0.0f;
    #pragma unroll 8
    for (int i = lane; i < DIM; i += 32) s += sx[i] * gwr[i];
    #pragma unroll
    for (int o = 16; o > 0; o >>= 1) s += __shfl_down_sync(0xffffffffu, s, o);
    if (lane == 0) {
        s += gb[w];
        slog[w] = s;
        if (logits_out) logits_out[(size_t)t * NE + w] = s;
    }
    __syncthreads();

    if (tid == 0) {
        int i0 = 0; float v0 = slog[0];
        #pragma unroll
        for (int i = 1; i < NE; i++) if (slog[i] > v0) { v0 = slog[i]; i0 = i; }
        int i1 = -1; float v1 = -3.4e38f;
        #pragma unroll
        for (int i = 0; i < NE; i++) if (i != i0 && slog[i] > v1) { v1 = slog[i]; i1 = i; }
        float r  = expf(v1 - v0);
        float w0 = 1.0f / (1.0f + r);
        float w1 = r * w0;

        int p0 = atomicAdd(&g_counts[i0], 1);
        g_lists[i0 * TMAX + p0] = t * 2;
        int p1 = atomicAdd(&g_counts[i1], 1);
        g_lists[i1 * TMAX + p1] = t * 2 + 1;
        g_wslot[t * 2]     = w0;
        g_wslot[t * 2 + 1] = w1;
    }
}

// ---------------- kernel 2: gathered tf32 GEMM1 + bias + exact GELU -> h_buf ----------------
// Tile 128x128, BK=16, 8 warps (4x2), warp tile 32x64, mma m16n8k8 tf32.
__global__ void __launch_bounds__(256, 2) gemm1_kernel(
    const float* __restrict__ x, const float* __restrict__ W1,
    const float* __restrict__ b1)
{
    const int e   = blockIdx.z;
    const int cnt = g_counts[e];
    const int m0  = blockIdx.y * 128;
    if (m0 >= cnt) return;
    const int n0  = blockIdx.x * 128;

    __shared__ __align__(16) float As[2][128][20];   // [m][k] rowstride 20 (conflict-free frags)
    __shared__ __align__(16) float Bs[2][16][136];   // [k][n] rowstride 136 (conflict-free frags)
    __shared__ int sSlot[128];

    const int tid = threadIdx.x;
    if (tid < 128) {
        int gr = m0 + tid;
        sSlot[tid] = (gr < cnt) ? g_lists[e * TMAX + gr] : -1;
    }
    __syncthreads();

    // A gather: thread -> (row ar, k-subchunk akv)
    const int ar  = tid >> 1;
    const int akv = (tid & 1) * 8;
    const int aslot = sSlot[ar];
    const float* aRow = x + (size_t)(aslot >= 0 ? (aslot >> 1) : 0) * DIM;
    // B: thread -> (k-row br, n-offset bn)
    const int br = tid >> 4;
    const int bn = (tid & 15) * 8;
    const float* Bg = W1 + (size_t)e * DIM * HID + (size_t)br * HID + n0 + bn;

    const int lane = tid & 31, wid = tid >> 5;
    const int warp_m = wid & 3, warp_n = wid >> 2;
    const int g = lane >> 2, t4 = lane & 3;

    float acc[2][8][4];
    #pragma unroll
    for (int mt = 0; mt < 2; mt++)
        #pragma unroll
        for (int nt = 0; nt < 8; nt++)
            #pragma unroll
            for (int i = 0; i < 4; i++) acc[mt][nt][i] = 0.0f;

    // prologue: stage 0
    cp16(&As[0][ar][akv],     aRow + akv);
    cp16(&As[0][ar][akv + 4], aRow + akv + 4);
    cp16(&Bs[0][br][bn],      Bg);
    cp16(&Bs[0][br][bn + 4],  Bg + 4);
    CP_COMMIT;
    CP_WAIT0;
    __syncthreads();

    const int KT = DIM / 16;
    int buf = 0;
    for (int kt = 0; kt < KT; kt++) {
        if (kt + 1 < KT) {
            const int ko = (kt + 1) * 16;
            cp16(&As[buf ^ 1][ar][akv],     aRow + ko + akv);
            cp16(&As[buf ^ 1][ar][akv + 4], aRow + ko + akv + 4);
            const float* bp = Bg + (size_t)ko * HID;
            cp16(&Bs[buf ^ 1][br][bn],     bp);
            cp16(&Bs[buf ^ 1][br][bn + 4], bp + 4);
            CP_COMMIT;
        }
        #pragma unroll
        for (int ks = 0; ks < 16; ks += 8) {
            unsigned a[2][4], b[8][2];
            #pragma unroll
            for (int mt = 0; mt < 2; mt++) {
                const int mb = warp_m * 32 + mt * 16 + g;
                a[mt][0] = f2tf(As[buf][mb][ks + t4]);
                a[mt][1] = f2tf(As[buf][mb + 8][ks + t4]);
                a[mt][2] = f2tf(As[buf][mb][ks + t4 + 4]);
                a[mt][3] = f2tf(As[buf][mb + 8][ks + t4 + 4]);
            }
            #pragma unroll
            for (int nt = 0; nt < 8; nt++) {
                const int nb = warp_n * 64 + nt * 8 + g;
                b[nt][0] = f2tf(Bs[buf][ks + t4][nb]);
                b[nt][1] = f2tf(Bs[buf][ks + t4 + 4][nb]);
            }
            #pragma unroll
            for (int mt = 0; mt < 2; mt++)
                #pragma unroll
                for (int nt = 0; nt < 8; nt++)
                    mma_tf32(acc[mt][nt], a[mt], b[nt]);
        }
        if (kt + 1 < KT) {
            CP_WAIT0;
            __syncthreads();
            buf ^= 1;
        }
    }

    // epilogue: bias + exact GELU, scatter rows to g_hbuf[slot]
    const float* b1g = b1 + (size_t)e * HID + n0;
    #pragma unroll
    for (int mt = 0; mt < 2; mt++) {
        const int r0 = warp_m * 32 + mt * 16 + g;
        const int r1 = r0 + 8;
        const bool v0 = (m0 + r0) < cnt;
        const bool v1 = (m0 + r1) < cnt;
        float* h0 = v0 ? (g_hbuf + (size_t)sSlot[r0] * HID + n0) : (float*)0;
        float* h1 = v1 ? (g_hbuf + (size_t)sSlot[r1] * HID + n0) : (float*)0;
        #pragma unroll
        for (int nt = 0; nt < 8; nt++) {
            const int n = warp_n * 64 + nt * 8 + t4 * 2;
            const float bb0 = b1g[n], bb1 = b1g[n + 1];
            if (v0) {
                float2 hv;
                hv.x = gelu_exact(acc[mt][nt][0] + bb0);
                hv.y = gelu_exact(acc[mt][nt][1] + bb1);
                *(float2*)(h0 + n) = hv;
            }
            if (v1) {
                float2 hv;
                hv.x = gelu_exact(acc[mt][nt][2] + bb0);
                hv.y = gelu_exact(acc[mt][nt][3] + bb1);
                *(float2*)(h1 + n) = hv;
            }
        }
    }
}

// ---------------- kernel 3: tf32 GEMM2 + bias, weighted atomic scatter to out ----------------
__global__ void __launch_bounds__(256, 2) gemm2_kernel(
    const float* __restrict__ W2, const float* __restrict__ b2,
    float* __restrict__ out)
{
    const int e   = blockIdx.z;
    const int cnt = g_counts[e];
    const int m0  = blockIdx.y * 128;
    if (m0 >= cnt) return;
    const int n0  = blockIdx.x * 128;

    __shared__ __align__(16) float As[2][128][20];
    __shared__ __align__(16) float Bs[2][16][136];
    __shared__ int sSlot[128];

    const int tid = threadIdx.x;
    if (tid < 128) {
        int gr = m0 + tid;
        sSlot[tid] = (gr < cnt) ? g_lists[e * TMAX + gr] : -1;
    }
    __syncthreads();

    const int ar  = tid >> 1;
    const int akv = (tid & 1) * 8;
    const int aslot = sSlot[ar];
    const float* aRow = g_hbuf + (size_t)(aslot >= 0 ? aslot : 0) * HID;
    const int br = tid >> 4;
    const int bn = (tid & 15) * 8;
    const float* Bg = W2 + (size_t)e * HID * DIM + (size_t)br * DIM + n0 + bn;

    const int lane = tid & 31, wid = tid >> 5;
    const int warp_m = wid & 3, warp_n = wid >> 2;
    const int g = lane >> 2, t4 = lane & 3;

    float acc[2][8][4];
    #pragma unroll
    for (int mt = 0; mt < 2; mt++)
        #pragma unroll
        for (int nt = 0; nt < 8; nt++)
            #pragma unroll
            for (int i = 0; i < 4; i++) acc[mt][nt][i] = 0.0f;

    cp16(&As[0][ar][akv],     aRow + akv);
    cp16(&As[0][ar][akv + 4], aRow + akv + 4);
    cp16(&Bs[0][br][bn],      Bg);
    cp16(&Bs[0][br][bn + 4],  Bg + 4);
    CP_COMMIT;
    CP_WAIT0;
    __syncthreads();

    const int KT = HID / 16;
    int buf = 0;
    for (int kt = 0; kt < KT; kt++) {
        if (kt + 1 < KT) {
            const int ko = (kt + 1) * 16;
            cp16(&As[buf ^ 1][ar][akv],     aRow + ko + akv);
            cp16(&As[buf ^ 1][ar][akv + 4], aRow + ko + akv + 4);
            const float* bp = Bg + (size_t)ko * DIM;
            cp16(&Bs[buf ^ 1][br][bn],     bp);
            cp16(&Bs[buf ^ 1][br][bn + 4], bp + 4);
            CP_COMMIT;
        }
        #pragma unroll
        for (int ks = 0; ks < 16; ks += 8) {
            unsigned a[2][4], b[8][2];
            #pragma unroll
            for (int mt = 0; mt < 2; mt++) {
                const int mb = warp_m * 32 + mt * 16 + g;
                a[mt][0] = f2tf(As[buf][mb][ks + t4]);
                a[mt][1] = f2tf(As[buf][mb + 8][ks + t4]);
                a[mt][2] = f2tf(As[buf][mb][ks + t4 + 4]);
                a[mt][3] = f2tf(As[buf][mb + 8][ks + t4 + 4]);
            }
            #pragma unroll
            for (int nt = 0; nt < 8; nt++) {
                const int nb = warp_n * 64 + nt * 8 + g;
                b[nt][0] = f2tf(Bs[buf][ks + t4][nb]);
                b[nt][1] = f2tf(Bs[buf][ks + t4 + 4][nb]);
            }
            #pragma unroll
            for (int mt = 0; mt < 2; mt++)
                #pragma unroll
                for (int nt = 0; nt < 8; nt++)
                    mma_tf32(acc[mt][nt], a[mt], b[nt]);
        }
        if (kt + 1 < KT) {
            CP_WAIT0;
            __syncthreads();
            buf ^= 1;
        }
    }

    // epilogue: v = w * (acc + bias), atomic scatter to out[token]
    const float* b2g = b2 + (size_t)e * DIM + n0;
    #pragma unroll
    for (int mt = 0; mt < 2; mt++) {
        const int r0 = warp_m * 32 + mt * 16 + g;
        const int r1 = r0 + 8;
        const bool v0 = (m0 + r0) < cnt;
        const bool v1 = (m0 + r1) < cnt;
        int   s0 = v0 ? sSlot[r0] : 0;
        int   s1 = v1 ? sSlot[r1] : 0;
        float w0 = v0 ? g_wslot[s0] : 0.0f;
        float w1 = v1 ? g_wslot[s1] : 0.0f;
        float* o0 = out + (size_t)(s0 >> 1) * DIM + n0;
        float* o1 = out + (size_t)(s1 >> 1) * DIM + n0;
        #pragma unroll
        for (int nt = 0; nt < 8; nt++) {
            const int n = warp_n * 64 + nt * 8 + t4 * 2;
            const float bb0 = b2g[n], bb1 = b2g[n + 1];
            if (v0) {
                atomicAdd(o0 + n,     w0 * (acc[mt][nt][0] + bb0));
                atomicAdd(o0 + n + 1, w0 * (acc[mt][nt][1] + bb1));
            }
            if (v1) {
                atomicAdd(o1 + n,     w1 * (acc[mt][nt][2] + bb0));
                atomicAdd(o1 + n + 1, w1 * (acc[mt][nt][3] + bb1));
            }
        }
    }
}

// ---------------- launch ----------------
extern "C" void kernel_launch(void* const* d_in, const int* in_sizes, int n_in,
                              void* d_out, int out_size)
{
    const float* x  = (const float*)d_in[0];
    const float* gw = (const float*)d_in[1];
    const float* gb = (const float*)d_in[2];
    const float* W1 = (const float*)d_in[3];
    const float* b1 = (const float*)d_in[4];
    const float* W2 = (const float*)d_in[5];
    const float* b2 = (const float*)d_in[6];
    float* out = (float*)d_out;

    const int T = in_sizes[0] / DIM;  // 8192

    float* logits = 0;
    if (out_size >= T * DIM + T * NE) logits = out + (size_t)T * DIM;

    cudaMemsetAsync(out, 0, (size_t)T * DIM * sizeof(float), 0);
    zero_counts_kernel<<<1, 32>>>();
    gating_kernel<<<T, 256>>>(x, gw, gb, logits);

    const int mt = (T + 127) / 128;   // worst-case M tiles per expert
    gemm1_kernel<<<dim3(HID / 128, mt, NE), 256>>>(x, W1, b1);
    gemm2_kernel<<<dim3(DIM / 128, mt, NE), 256>>>(W2, b2, out);
}

// round 5
// speedup vs baseline: 2.6082x; 1.0518x over previous
#include <cuda_runtime.h>
#include <cstdint>
#include <math.h>

#define DIM   1024
#define HID   2048
#define NE    8
#define TMAX  8192
#define NSLOT (TMAX * 2)

// GEMM tiling
#define BM 128
#define BN 128
#define BK 16
#define RSB 80                               // row stride bytes (20 floats, LDSM conflict-free)
#define A_STAGE_BYTES (BM * RSB)             // 10240
#define B_STAGE_BYTES (BN * RSB)             // 10240
#define STAGE_BYTES   (A_STAGE_BYTES + B_STAGE_BYTES)
#define SMEM_BYTES    (2 * STAGE_BYTES)      // 40960

// ---------------- static device scratch (round-2 footprint: ~128 MB) ----------------
__device__ int   g_counts[NE];
__device__ int   g_lists[NE * TMAX];
__device__ float g_wslot[NSLOT];
__device__ float g_hbuf[(size_t)NSLOT * HID];   // tf32-pre-rounded hidden acts

// ---------------- helpers ----------------
__device__ __forceinline__ float tf32r(float f) {
    uint32_t u;
    asm("cvt.rna.tf32.f32 %0, %1;" : "=r"(u) : "f"(f));
    return __uint_as_float(u);
}
__device__ __forceinline__ float gelu_exact(float v) {
    return 0.5f * v * (1.0f + erff(v * 0.7071067811865476f));
}
__device__ __forceinline__ uint32_t smem_u32(const void* p) {
    return (uint32_t)__cvta_generic_to_shared(p);
}
__device__ __forceinline__ void mma_tf32(float* c, const uint32_t* a, const uint32_t* b) {
    asm volatile(
        "mma.sync.aligned.m16n8k8.row.col.f32.tf32.tf32.f32 "
        "{%0,%1,%2,%3}, {%4,%5,%6,%7}, {%8,%9}, {%0,%1,%2,%3};"
        : "+f"(c[0]), "+f"(c[1]), "+f"(c[2]), "+f"(c[3])
        : "r"(a[0]), "r"(a[1]), "r"(a[2]), "r"(a[3]), "r"(b[0]), "r"(b[1]));
}
__device__ __forceinline__ void ldsm4(uint32_t* d, uint32_t addr) {
    asm volatile("ldmatrix.sync.aligned.m8n8.x4.shared.b16 {%0,%1,%2,%3}, [%4];"
        : "=r"(d[0]), "=r"(d[1]), "=r"(d[2]), "=r"(d[3]) : "r"(addr));
}

// ---------------- kernel 0: zero routing counters ----------------
__global__ void zero_counts_kernel() {
    if (threadIdx.x < NE) g_counts[threadIdx.x] = 0;
}

// ---------------- gating ----------------
__global__ void __launch_bounds__(256) gating_kernel(
    const float* __restrict__ x, const float* __restrict__ gw,
    const float* __restrict__ gb, float* __restrict__ logits_out)
{
    const int t = blockIdx.x;
    __shared__ float sx[DIM];
    __shared__ float slog[NE];
    const int tid = threadIdx.x;
    const float* xr = x + (size_t)t * DIM;
    #pragma unroll 2
    for (int i = tid; i < DIM; i += 256) sx[i] = xr[i];
    __syncthreads();

    const int w = tid >> 5, lane = tid & 31;
    const float* gwr = gw + (size_t)w * DIM;
    float s = 0.0f;
    #pragma unroll 8
    for (int i = lane; i < DIM; i += 32) s += sx[i] * gwr[i];
    #pragma unroll
    for (int o = 16; o > 0; o >>= 1) s += __shfl_down_sync(0xffffffffu, s, o);
    if (lane == 0) {
        s += gb[w];
        slog[w] = s;
        if (logits_out) logits_out[(size_t)t * NE + w] = s;
    }
    __syncthreads();

    if (tid == 0) {
        int i0 = 0; float v0 = slog[0];
        #pragma unroll
        for (int i = 1; i < NE; i++) if (slog[i] > v0) { v0 = slog[i]; i0 = i; }
        int i1 = -1; float v1 = -3.4e38f;
        #pragma unroll
        for (int i = 0; i < NE; i++) if (i != i0 && slog[i] > v1) { v1 = slog[i]; i1 = i; }
        float r  = expf(v1 - v0);
        float w0 = 1.0f / (1.0f + r);
        float w1 = r * w0;
        int p0 = atomicAdd(&g_counts[i0], 1);
        g_lists[i0 * TMAX + p0] = t * 2;
        int p1 = atomicAdd(&g_counts[i1], 1);
        g_lists[i1 * TMAX + p1] = t * 2 + 1;
        g_wslot[t * 2]     = w0;
        g_wslot[t * 2 + 1] = w1;
    }
}

// ---------------- shared tf32 mma mainloop ----------------
// A smem [BM][20] (row-major, k contiguous); B smem [BN][20] (n rows, k contiguous).
// Fill: LDG -> (round) -> STS, double-buffered, one __syncthreads per K-chunk.
// Fragments: ldmatrix m8n8.b16 x4 interpreted as 8x4 tf32 tiles.
template <int KT, bool CVTA>
__device__ __forceinline__ void mma_mainloop(
    char* sm, const float* aPtr, const float* bPtr, int ldB,
    uint32_t fillOff, int warp_m, int warp_n, int lane,
    float acc[2][8][4])
{
    // ldmatrix lane address bases
    const int a_row = ((lane >> 3) & 1) * 8 + (lane & 7);
    const int a_k   = ((lane >> 4) & 1) * 4;
    const int b_n   = (lane & 7) + ((lane >> 4) & 1) * 8;
    const int b_k   = ((lane >> 3) & 1) * 4;
    const uint32_t sbase = smem_u32(sm);
    const uint32_t aAddr = sbase + (uint32_t)(warp_m * 32 + a_row) * RSB + a_k * 4;
    const uint32_t bAddr = sbase + A_STAGE_BYTES + (uint32_t)(warp_n * 64 + b_n) * RSB + b_k * 4;

    float4 ra0, ra1;
    float  rb[8];

    auto ldg = [&](int kt) {
        const float* ap = aPtr + kt * BK;
        ra0 = *(const float4*)ap;
        ra1 = *(const float4*)(ap + 4);
        const float* bp = bPtr + (size_t)kt * BK * ldB;
        #pragma unroll
        for (int j = 0; j < 8; j++) rb[j] = bp[(size_t)j * ldB];
    };
    auto sts = [&](int stage) {
        char* as = sm + stage * STAGE_BYTES + fillOff;
        float4 v0 = ra0, v1 = ra1;
        if (CVTA) {
            v0.x = tf32r(v0.x); v0.y = tf32r(v0.y); v0.z = tf32r(v0.z); v0.w = tf32r(v0.w);
            v1.x = tf32r(v1.x); v1.y = tf32r(v1.y); v1.z = tf32r(v1.z); v1.w = tf32r(v1.w);
        }
        *(float4*)as = v0;
        *(float4*)(as + 16) = v1;
        char* bs = sm + stage * STAGE_BYTES + A_STAGE_BYTES + fillOff;
        float4 w0, w1;
        w0.x = tf32r(rb[0]); w0.y = tf32r(rb[1]); w0.z = tf32r(rb[2]); w0.w = tf32r(rb[3]);
        w1.x = tf32r(rb[4]); w1.y = tf32r(rb[5]); w1.z = tf32r(rb[6]); w1.w = tf32r(rb[7]);
        *(float4*)bs = w0;
        *(float4*)(bs + 16) = w1;
    };

    // prologue
    ldg(0);
    sts(0);
    ldg(1);
    __syncthreads();

    for (int kt = 0; kt < KT; kt++) {
        if (kt + 1 < KT) sts((kt + 1) & 1);    // other buffer; safe after prior sync
        if (kt + 2 < KT) ldg(kt + 2);

        const uint32_t st = (uint32_t)(kt & 1) * STAGE_BYTES;
        #pragma unroll
        for (int ks = 0; ks < BK; ks += 8) {
            uint32_t a[2][4];
            ldsm4(a[0], aAddr + st + ks * 4);
            ldsm4(a[1], aAddr + st + 16 * RSB + ks * 4);
            #pragma unroll
            for (int ntp = 0; ntp < 4; ntp++) {
                uint32_t b[4];
                ldsm4(b, bAddr + st + ntp * 16 * RSB + ks * 4);
                mma_tf32(acc[0][2 * ntp],     a[0], b);
                mma_tf32(acc[1][2 * ntp],     a[1], b);
                mma_tf32(acc[0][2 * ntp + 1], a[0], b + 2);
                mma_tf32(acc[1][2 * ntp + 1], a[1], b + 2);
            }
        }
        __syncthreads();
    }
}

// ---------------- GEMM1: h = round(gelu(x_e @ W1 + b1)) -> g_hbuf ----------------
__global__ void __launch_bounds__(256, 2) gemm1_kernel(
    const float* __restrict__ x, const float* __restrict__ W1,
    const float* __restrict__ b1)
{
    const int e   = blockIdx.z;
    const int cnt = g_counts[e];
    const int m0  = blockIdx.y * BM;
    if (m0 >= cnt) return;
    const int n0  = blockIdx.x * BN;

    extern __shared__ char smem[];
    __shared__ int sSlot[BM];

    const int tid = threadIdx.x, wid = tid >> 5, lane = tid & 31;
    if (tid < BM) {
        int gr = m0 + tid;
        sSlot[tid] = (gr < cnt) ? g_lists[e * TMAX + gr] : -1;
    }
    __syncthreads();

    const int frow = tid & 127, fhalf = tid >> 7;
    const int aslot = sSlot[frow];
    const float* aPtr = x + (size_t)(aslot >= 0 ? (aslot >> 1) : 0) * DIM + fhalf * 8;
    const float* bPtr = W1 + (size_t)e * DIM * HID + (size_t)(fhalf * 8) * HID + n0 + frow;
    const uint32_t fillOff = (uint32_t)frow * RSB + fhalf * 32;

    const int warp_m = wid & 3, warp_n = wid >> 2;
    const int g = lane >> 2, t4 = lane & 3;

    float acc[2][8][4];
    #pragma unroll
    for (int mt = 0; mt < 2; mt++)
        #pragma unroll
        for (int nt = 0; nt < 8; nt++)
            #pragma unroll
            for (int i = 0; i < 4; i++) acc[mt][nt][i] = 0.0f;

    mma_mainloop<DIM / BK, true>(smem, aPtr, bPtr, HID, fillOff, warp_m, warp_n, lane, acc);

    // epilogue: bias + exact GELU, tf32-round, scatter rows to g_hbuf[slot]
    const float* b1g = b1 + (size_t)e * HID + n0;
    #pragma unroll
    for (int mt = 0; mt < 2; mt++) {
        const int r0 = warp_m * 32 + mt * 16 + g;
        const int r1 = r0 + 8;
        const bool v0 = (m0 + r0) < cnt;
        const bool v1 = (m0 + r1) < cnt;
        float* h0 = v0 ? (g_hbuf + (size_t)sSlot[r0] * HID + n0) : (float*)0;
        float* h1 = v1 ? (g_hbuf + (size_t)sSlot[r1] * HID + n0) : (float*)0;
        #pragma unroll
        for (int nt = 0; nt < 8; nt++) {
            const int col = warp_n * 64 + nt * 8 + 2 * t4;
            const float bb0 = b1g[col], bb1 = b1g[col + 1];
            if (v0) {
                float2 hv;
                hv.x = tf32r(gelu_exact(acc[mt][nt][0] + bb0));
                hv.y = tf32r(gelu_exact(acc[mt][nt][1] + bb1));
                *(float2*)(h0 + col) = hv;
            }
            if (v1) {
                float2 hv;
                hv.x = tf32r(gelu_exact(acc[mt][nt][2] + bb0));
                hv.y = tf32r(gelu_exact(acc[mt][nt][3] + bb1));
                *(float2*)(h1 + col) = hv;
            }
        }
    }
}

// ---------------- GEMM2: out[token] += w * (h_e @ W2 + b2) ----------------
__global__ void __launch_bounds__(256, 2) gemm2_kernel(
    const float* __restrict__ W2, const float* __restrict__ b2,
    float* __restrict__ out)
{
    const int e   = blockIdx.z;
    const int cnt = g_counts[e];
    const int m0  = blockIdx.y * BM;
    if (m0 >= cnt) return;
    const int n0  = blockIdx.x * BN;

    extern __shared__ char smem[];
    __shared__ int sSlot[BM];

    const int tid = threadIdx.x, wid = tid >> 5, lane = tid & 31;
    if (tid < BM) {
        int gr = m0 + tid;
        sSlot[tid] = (gr < cnt) ? g_lists[e * TMAX + gr] : -1;
    }
    __syncthreads();

    const int frow = tid & 127, fhalf = tid >> 7;
    const int aslot = sSlot[frow];
    const float* aPtr = g_hbuf + (size_t)(aslot >= 0 ? aslot : 0) * HID + fhalf * 8;
    const float* bPtr = W2 + (size_t)e * HID * DIM + (size_t)(fhalf * 8) * DIM + n0 + frow;
    const uint32_t fillOff = (uint32_t)frow * RSB + fhalf * 32;

    const int warp_m = wid & 3, warp_n = wid >> 2;
    const int g = lane >> 2, t4 = lane & 3;

    float acc[2][8][4];
    #pragma unroll
    for (int mt = 0; mt < 2; mt++)
        #pragma unroll
        for (int nt = 0; nt < 8; nt++)
            #pragma unroll
            for (int i = 0; i < 4; i++) acc[mt][nt][i] = 0.0f;

    mma_mainloop<HID / BK, false>(smem, aPtr, bPtr, DIM, fillOff, warp_m, warp_n, lane, acc);

    // epilogue: v = w * (acc + bias), atomic scatter to out[token]
    const float* b2g = b2 + (size_t)e * DIM + n0;
    #pragma unroll
    for (int mt = 0; mt < 2; mt++) {
        const int r0 = warp_m * 32 + mt * 16 + g;
        const int r1 = r0 + 8;
        const bool v0 = (m0 + r0) < cnt;
        const bool v1 = (m0 + r1) < cnt;
        int   s0 = v0 ? sSlot[r0] : 0;
        int   s1 = v1 ? sSlot[r1] : 0;
        float w0 = v0 ? g_wslot[s0] : 0.0f;
        float w1 = v1 ? g_wslot[s1] : 0.0f;
        float* o0 = out + (size_t)(s0 >> 1) * DIM + n0;
        float* o1 = out + (size_t)(s1 >> 1) * DIM + n0;
        #pragma unroll
        for (int nt = 0; nt < 8; nt++) {
            const int col = warp_n * 64 + nt * 8 + 2 * t4;
            const float bb0 = b2g[col], bb1 = b2g[col + 1];
            if (v0) {
                atomicAdd(o0 + col,     w0 * (acc[mt][nt][0] + bb0));
                atomicAdd(o0 + col + 1, w0 * (acc[mt][nt][1] + bb1));
            }
            if (v1) {
                atomicAdd(o1 + col,     w1 * (acc[mt][nt][2] + bb0));
                atomicAdd(o1 + col + 1, w1 * (acc[mt][nt][3] + bb1));
            }
        }
    }
}

// ---------------- launch ----------------
extern "C" void kernel_launch(void* const* d_in, const int* in_sizes, int n_in,
                              void* d_out, int out_size)
{
    const float* x  = (const float*)d_in[0];
    const float* gw = (const float*)d_in[1];
    const float* gb = (const float*)d_in[2];
    const float* W1 = (const float*)d_in[3];
    const float* b1 = (const float*)d_in[4];
    const float* W2 = (const float*)d_in[5];
    const float* b2 = (const float*)d_in[6];
    float* out = (float*)d_out;

    const int T = in_sizes[0] / DIM;  // 8192
    float* logits = 0;
    if (out_size >= T * DIM + T * NE) logits = out + (size_t)T * DIM;

    cudaMemsetAsync(out, 0, (size_t)T * DIM * sizeof(float), 0);
    zero_counts_kernel<<<1, 32>>>();
    gating_kernel<<<T, 256>>>(x, gw, gb, logits);

    const int mt = T / BM;  // worst-case M tiles per expert (64)
    gemm1_kernel<<<dim3(HID / BN, mt, NE), 256, SMEM_BYTES>>>(x, W1, b1);
    gemm2_kernel<<<dim3(DIM / BN, mt, NE), 256, SMEM_BYTES>>>(W2, b2, out);
}

// round 6
// speedup vs baseline: 2.7025x; 1.0362x over previous
#include <cuda_runtime.h>
#include <cstdint>
#include <math.h>

#define DIM   1024
#define HID   2048
#define NE    8
#define TMAX  8192
#define NSLOT (TMAX * 2)

// GEMM tiling: CTA 128x256, 8 warps (2m x 4n), warp tile 64x64
#define BM 128
#define BN 256
#define BK 16
#define RSB 80                               // row stride bytes (20 floats, LDSM conflict-free)
#define A_STAGE_BYTES (BM * RSB)             // 10240
#define B_STAGE_BYTES (BN * RSB)             // 20480
#define STAGE_BYTES   (A_STAGE_BYTES + B_STAGE_BYTES)
#define SMEM_BYTES    (2 * STAGE_BYTES)      // 61440

// ---------------- static device scratch (~128 MB, round-2 footprint) ----------------
__device__ int   g_counts[NE];
__device__ int   g_lists[NE * TMAX];
__device__ float g_wslot[NSLOT];
__device__ float g_hbuf[(size_t)NSLOT * HID];   // tf32-pre-rounded hidden acts

// ---------------- helpers ----------------
__device__ __forceinline__ float tf32r(float f) {
    uint32_t u;
    asm("cvt.rna.tf32.f32 %0, %1;" : "=r"(u) : "f"(f));
    return __uint_as_float(u);
}
__device__ __forceinline__ float gelu_exact(float v) {
    return 0.5f * v * (1.0f + erff(v * 0.7071067811865476f));
}
__device__ __forceinline__ uint32_t smem_u32(const void* p) {
    return (uint32_t)__cvta_generic_to_shared(p);
}
__device__ __forceinline__ void mma_tf32(float* c, const uint32_t* a, const uint32_t* b) {
    asm volatile(
        "mma.sync.aligned.m16n8k8.row.col.f32.tf32.tf32.f32 "
        "{%0,%1,%2,%3}, {%4,%5,%6,%7}, {%8,%9}, {%0,%1,%2,%3};"
        : "+f"(c[0]), "+f"(c[1]), "+f"(c[2]), "+f"(c[3])
        : "r"(a[0]), "r"(a[1]), "r"(a[2]), "r"(a[3]), "r"(b[0]), "r"(b[1]));
}
__device__ __forceinline__ void ldsm4(uint32_t* d, uint32_t addr) {
    asm volatile("ldmatrix.sync.aligned.m8n8.x4.shared.b16 {%0,%1,%2,%3}, [%4];"
        : "=r"(d[0]), "=r"(d[1]), "=r"(d[2]), "=r"(d[3]) : "r"(addr));
}

// ---------------- kernel 0: zero routing counters ----------------
__global__ void zero_counts_kernel() {
    if (threadIdx.x < NE) g_counts[threadIdx.x] = 0;
}

// ---------------- gating ----------------
__global__ void __launch_bounds__(256) gating_kernel(
    const float* __restrict__ x, const float* __restrict__ gw,
    const float* __restrict__ gb, float* __restrict__ logits_out)
{
    const int t = blockIdx.x;
    __shared__ float sx[DIM];
    __shared__ float slog[NE];
    const int tid = threadIdx.x;
    const float* xr = x + (size_t)t * DIM;
    #pragma unroll 2
    for (int i = tid; i < DIM; i += 256) sx[i] = xr[i];
    __syncthreads();

    const int w = tid >> 5, lane = tid & 31;
    const float* gwr = gw + (size_t)w * DIM;
    float s = 0.0f;
    #pragma unroll 8
    for (int i = lane; i < DIM; i += 32) s += sx[i] * gwr[i];
    #pragma unroll
    for (int o = 16; o > 0; o >>= 1) s += __shfl_down_sync(0xffffffffu, s, o);
    if (lane == 0) {
        s += gb[w];
        slog[w] = s;
        if (logits_out) logits_out[(size_t)t * NE + w] = s;
    }
    __syncthreads();

    if (tid == 0) {
        int i0 = 0; float v0 = slog[0];
        #pragma unroll
        for (int i = 1; i < NE; i++) if (slog[i] > v0) { v0 = slog[i]; i0 = i; }
        int i1 = -1; float v1 = -3.4e38f;
        #pragma unroll
        for (int i = 0; i < NE; i++) if (i != i0 && slog[i] > v1) { v1 = slog[i]; i1 = i; }
        float r  = expf(v1 - v0);
        float w0 = 1.0f / (1.0f + r);
        float w1 = r * w0;
        int p0 = atomicAdd(&g_counts[i0], 1);
        g_lists[i0 * TMAX + p0] = t * 2;
        int p1 = atomicAdd(&g_counts[i1], 1);
        g_lists[i1 * TMAX + p1] = t * 2 + 1;
        g_wslot[t * 2]     = w0;
        g_wslot[t * 2 + 1] = w1;
    }
}

// ---------------- shared tf32 mma mainloop ----------------
// A smem [BM][20] (m rows, k contiguous); B smem [BN][20] (n rows, k contiguous).
// Fill: LDG -> (round) -> STS, double-buffered, one __syncthreads per K-chunk.
// Fragments: ldmatrix m8n8.b16 x4 interpreted as 8x4 tf32 tiles.
template <int KT, bool CVTA>
__device__ __forceinline__ void mma_mainloop(
    char* sm, const float* aPtr, const float* bPtr, int ldB,
    uint32_t aFillOff, uint32_t bFillOff,
    int warp_m, int warp_n, int lane,
    float acc[4][8][4])
{
    // ldmatrix lane address bases (validated mapping from round 5)
    const int a_row = ((lane >> 3) & 1) * 8 + (lane & 7);
    const int a_k   = ((lane >> 4) & 1) * 4;
    const int b_n   = (lane & 7) + ((lane >> 4) & 1) * 8;
    const int b_k   = ((lane >> 3) & 1) * 4;
    const uint32_t sbase = smem_u32(sm);
    const uint32_t aAddr = sbase + (uint32_t)(warp_m * 64 + a_row) * RSB + a_k * 4;
    const uint32_t bAddr = sbase + A_STAGE_BYTES + (uint32_t)(warp_n * 64 + b_n) * RSB + b_k * 4;

    float4 ra0, ra1;
    float  rb[16];

    auto ldg = [&](int kt) {
        const float* ap = aPtr + kt * BK;
        ra0 = *(const float4*)ap;
        ra1 = *(const float4*)(ap + 4);
        const float* bp = bPtr + (size_t)kt * BK * ldB;
        #pragma unroll
        for (int j = 0; j < 16; j++) rb[j] = bp[(size_t)j * ldB];
    };
    auto sts = [&](int stage) {
        char* as = sm + stage * STAGE_BYTES + aFillOff;
        float4 v0 = ra0, v1 = ra1;
        if (CVTA) {
            v0.x = tf32r(v0.x); v0.y = tf32r(v0.y); v0.z = tf32r(v0.z); v0.w = tf32r(v0.w);
            v1.x = tf32r(v1.x); v1.y = tf32r(v1.y); v1.z = tf32r(v1.z); v1.w = tf32r(v1.w);
        }
        *(float4*)as = v0;
        *(float4*)(as + 16) = v1;
        char* bs = sm + stage * STAGE_BYTES + A_STAGE_BYTES + bFillOff;
        #pragma unroll
        for (int q = 0; q < 4; q++) {
            float4 w;
            w.x = tf32r(rb[4 * q + 0]); w.y = tf32r(rb[4 * q + 1]);
            w.z = tf32r(rb[4 * q + 2]); w.w = tf32r(rb[4 * q + 3]);
            *(float4*)(bs + 16 * q) = w;
        }
    };

    // prologue
    ldg(0);
    sts(0);
    ldg(1);
    __syncthreads();

    for (int kt = 0; kt < KT; kt++) {
        if (kt + 1 < KT) sts((kt + 1) & 1);   // other buffer; safe after prior sync
        if (kt + 2 < KT) ldg(kt + 2);

        const uint32_t st = (uint32_t)(kt & 1) * STAGE_BYTES;
        #pragma unroll
        for (int ks = 0; ks < BK; ks += 8) {
            uint32_t a[4][4];
            #pragma unroll
            for (int mt = 0; mt < 4; mt++)
                ldsm4(a[mt], aAddr + st + mt * 16 * RSB + ks * 4);
            #pragma unroll
            for (int ntp = 0; ntp < 4; ntp++) {
                uint32_t b[4];
                ldsm4(b, bAddr + st + ntp * 16 * RSB + ks * 4);
                #pragma unroll
                for (int mt = 0; mt < 4; mt++) {
                    mma_tf32(acc[mt][2 * ntp],     a[mt], b);
                    mma_tf32(acc[mt][2 * ntp + 1], a[mt], b + 2);
                }
            }
        }
        __syncthreads();
    }
}

// ---------------- GEMM1: h = round(gelu(x_e @ W1 + b1)) -> g_hbuf ----------------
__global__ void __launch_bounds__(256, 1) gemm1_kernel(
    const float* __restrict__ x, const float* __restrict__ W1,
    const float* __restrict__ b1)
{
    const int e   = blockIdx.z;
    const int cnt = g_counts[e];
    const int m0  = blockIdx.y * BM;
    if (m0 >= cnt) return;
    const int n0  = blockIdx.x * BN;

    extern __shared__ char smem[];
    __shared__ int sSlot[BM];

    const int tid = threadIdx.x, wid = tid >> 5, lane = tid & 31;
    if (tid < BM) {
        int gr = m0 + tid;
        sSlot[tid] = (gr < cnt) ? g_lists[e * TMAX + gr] : -1;
    }
    __syncthreads();

    // A fill: thread -> (row frow, k-half fhalf); B fill: thread -> n-column tid
    const int frow = tid & 127, fhalf = tid >> 7;
    const int aslot = sSlot[frow];
    const float* aPtr = x + (size_t)(aslot >= 0 ? (aslot >> 1) : 0) * DIM + fhalf * 8;
    const float* bPtr = W1 + (size_t)e * DIM * HID + n0 + tid;
    const uint32_t aFillOff = (uint32_t)frow * RSB + fhalf * 32;
    const uint32_t bFillOff = (uint32_t)tid * RSB;

    const int warp_m = wid & 1, warp_n = wid >> 1;
    const int g = lane >> 2, t4 = lane & 3;

    float acc[4][8][4];
    #pragma unroll
    for (int mt = 0; mt < 4; mt++)
        #pragma unroll
        for (int nt = 0; nt < 8; nt++)
            #pragma unroll
            for (int i = 0; i < 4; i++) acc[mt][nt][i] = 0.0f;

    mma_mainloop<DIM / BK, true>(smem, aPtr, bPtr, HID, aFillOff, bFillOff,
                                 warp_m, warp_n, lane, acc);

    // epilogue: bias + exact GELU, tf32-round, scatter rows to g_hbuf[slot]
    const float* b1g = b1 + (size_t)e * HID + n0;
    #pragma unroll
    for (int mt = 0; mt < 4; mt++) {
        const int r0 = warp_m * 64 + mt * 16 + g;
        const int r1 = r0 + 8;
        const bool v0 = (m0 + r0) < cnt;
        const bool v1 = (m0 + r1) < cnt;
        float* h0 = v0 ? (g_hbuf + (size_t)sSlot[r0] * HID + n0) : (float*)0;
        float* h1 = v1 ? (g_hbuf + (size_t)sSlot[r1] * HID + n0) : (float*)0;
        #pragma unroll
        for (int nt = 0; nt < 8; nt++) {
            const int col = warp_n * 64 + nt * 8 + 2 * t4;
            const float bb0 = b1g[col], bb1 = b1g[col + 1];
            if (v0) {
                float2 hv;
                hv.x = tf32r(gelu_exact(acc[mt][nt][0] + bb0));
                hv.y = tf32r(gelu_exact(acc[mt][nt][1] + bb1));
                *(float2*)(h0 + col) = hv;
            }
            if (v1) {
                float2 hv;
                hv.x = tf32r(gelu_exact(acc[mt][nt][2] + bb0));
                hv.y = tf32r(gelu_exact(acc[mt][nt][3] + bb1));
                *(float2*)(h1 + col) = hv;
            }
        }
    }
}

// ---------------- GEMM2: out[token] += w * (h_e @ W2 + b2) ----------------
__global__ void __launch_bounds__(256, 1) gemm2_kernel(
    const float* __restrict__ W2, const float* __restrict__ b2,
    float* __restrict__ out)
{
    const int e   = blockIdx.z;
    const int cnt = g_counts[e];
    const int m0  = blockIdx.y * BM;
    if (m0 >= cnt) return;
    const int n0  = blockIdx.x * BN;

    extern __shared__ char smem[];
    __shared__ int sSlot[BM];

    const int tid = threadIdx.x, wid = tid >> 5, lane = tid & 31;
    if (tid < BM) {
        int gr = m0 + tid;
        sSlot[tid] = (gr < cnt) ? g_lists[e * TMAX + gr] : -1;
    }
    __syncthreads();

    const int frow = tid & 127, fhalf = tid >> 7;
    const int aslot = sSlot[frow];
    const float* aPtr = g_hbuf + (size_t)(aslot >= 0 ? aslot : 0) * HID + fhalf * 8;
    const float* bPtr = W2 + (size_t)e * HID * DIM + n0 + tid;
    const uint32_t aFillOff = (uint32_t)frow * RSB + fhalf * 32;
    const uint32_t bFillOff = (uint32_t)tid * RSB;

    const int warp_m = wid & 1, warp_n = wid >> 1;
    const int g = lane >> 2, t4 = lane & 3;

    float acc[4][8][4];
    #pragma unroll
    for (int mt = 0; mt < 4; mt++)
        #pragma unroll
        for (int nt = 0; nt < 8; nt++)
            #pragma unroll
            for (int i = 0; i < 4; i++) acc[mt][nt][i] = 0.0f;

    mma_mainloop<HID / BK, false>(smem, aPtr, bPtr, DIM, aFillOff, bFillOff,
                                  warp_m, warp_n, lane, acc);

    // epilogue: v = w * (acc + bias), atomic scatter to out[token]
    const float* b2g = b2 + (size_t)e * DIM + n0;
    #pragma unroll
    for (int mt = 0; mt < 4; mt++) {
        const int r0 = warp_m * 64 + mt * 16 + g;
        const int r1 = r0 + 8;
        const bool v0 = (m0 + r0) < cnt;
        const bool v1 = (m0 + r1) < cnt;
        int   s0 = v0 ? sSlot[r0] : 0;
        int   s1 = v1 ? sSlot[r1] : 0;
        float w0 = v0 ? g_wslot[s0] : 0.0f;
        float w1 = v1 ? g_wslot[s1] : 0.0f;
        float* o0 = out + (size_t)(s0 >> 1) * DIM + n0;
        float* o1 = out + (size_t)(s1 >> 1) * DIM + n0;
        #pragma unroll
        for (int nt = 0; nt < 8; nt++) {
            const int col = warp_n * 64 + nt * 8 + 2 * t4;
            const float bb0 = b2g[col], bb1 = b2g[col + 1];
            if (v0) {
                atomicAdd(o0 + col,     w0 * (acc[mt][nt][0] + bb0));
                atomicAdd(o0 + col + 1, w0 * (acc[mt][nt][1] + bb1));
            }
            if (v1) {
                atomicAdd(o1 + col,     w1 * (acc[mt][nt][2] + bb0));
                atomicAdd(o1 + col + 1, w1 * (acc[mt][nt][3] + bb1));
            }
        }
    }
}

// ---------------- launch ----------------
extern "C" void kernel_launch(void* const* d_in, const int* in_sizes, int n_in,
                              void* d_out, int out_size)
{
    const float* x  = (const float*)d_in[0];
    const float* gw = (const float*)d_in[1];
    const float* gb = (const float*)d_in[2];
    const float* W1 = (const float*)d_in[3];
    const float* b1 = (const float*)d_in[4];
    const float* W2 = (const float*)d_in[5];
    const float* b2 = (const float*)d_in[6];
    float* out = (float*)d_out;

    const int T = in_sizes[0] / DIM;  // 8192
    float* logits = 0;
    if (out_size >= T * DIM + T * NE) logits = out + (size_t)T * DIM;

    cudaFuncSetAttribute(gemm1_kernel, cudaFuncAttributeMaxDynamicSharedMemorySize, SMEM_BYTES);
    cudaFuncSetAttribute(gemm2_kernel, cudaFuncAttributeMaxDynamicSharedMemorySize, SMEM_BYTES);

    cudaMemsetAsync(out, 0, (size_t)T * DIM * sizeof(float), 0);
    zero_counts_kernel<<<1, 32>>>();
    gating_kernel<<<T, 256>>>(x, gw, gb, logits);

    const int mt = T / BM;  // worst-case M tiles per expert (64)
    gemm1_kernel<<<dim3(HID / BN, mt, NE), 256, SMEM_BYTES>>>(x, W1, b1);
    gemm2_kernel<<<dim3(DIM / BN, mt, NE), 256, SMEM_BYTES>>>(W2, b2, out);
}